// round 5
// baseline (speedup 1.0000x reference)
#include <cuda_runtime.h>
#include <cuda_fp16.h>
#include <cstdint>
#include <math.h>

#define HDIM   512
#define BDIM   512
#define GDIM   2048
#define NSTEPS 30
#define BH     (BDIM * HDIM)
#define BH2    (BDIM * 256)          // half2 per [512,512] plane
#define WSZ    ((size_t)GDIM * HDIM) // fp32 weight plane elems

__device__ __align__(1024) __half2 g_x16[NSTEPS * BH2];  // 15.7 MB
__device__ __align__(1024) __half2 g_h16[4 * BH2];       // [parity][layer], 2 MB
__device__ __align__(1024) float   g_c[2 * BH];          // 2 MB

// ---------------- helpers ----------------
__device__ __forceinline__ uint32_t smem_u32(const void* p) {
    uint32_t a;
    asm("{ .reg .u64 t; cvta.to.shared.u64 t, %1; cvt.u32.u64 %0, t; }" : "=r"(a) : "l"(p));
    return a;
}
#define CP_ASYNC16(dst_u32, src_ptr) \
    asm volatile("cp.async.cg.shared.global [%0], [%1], 16;" \
                 :: "r"(dst_u32), "l"(src_ptr) : "memory")
#define CP_COMMIT() asm volatile("cp.async.commit_group;" ::: "memory")
#define CP_WAIT2()  asm volatile("cp.async.wait_group 2;" ::: "memory")
#define STS128(addr, v) \
    asm volatile("st.shared.v4.b32 [%0], {%1,%2,%3,%4};" \
                 :: "r"(addr), "r"((v).x), "r"((v).y), "r"((v).z), "r"((v).w) : "memory")

__device__ __forceinline__ void mma_f16(float* d,
                                        uint32_t a0, uint32_t a1, uint32_t a2, uint32_t a3,
                                        uint32_t b0, uint32_t b1) {
    asm volatile(
        "mma.sync.aligned.m16n8k16.row.col.f32.f16.f16.f32 "
        "{%0,%1,%2,%3}, {%4,%5,%6,%7}, {%8,%9}, {%0,%1,%2,%3};"
        : "+f"(d[0]), "+f"(d[1]), "+f"(d[2]), "+f"(d[3])
        : "r"(a0), "r"(a1), "r"(a2), "r"(a3), "r"(b0), "r"(b1));
}
__device__ __forceinline__ float fast_sigmoid(float x) {
    return __fdividef(1.0f, 1.0f + __expf(-x));
}
__device__ __forceinline__ float fast_tanh(float x) {
    return 1.0f - __fdividef(2.0f, __expf(2.0f * x) + 1.0f);
}
__device__ __forceinline__ uint32_t pk(float a, float b) {
    __half2 h = __floats2half2_rn(a, b);
    return *reinterpret_cast<uint32_t*>(&h);
}

// ---------------- smem layout ----------------
// stage: A 64x32 half (4096 B, permuted rows of 64 B) + W 128x32 half (8192 B)
#define NSTAGE   4
#define STAGE_B  12288
#define OFF_W    4096
#define BIAS_OFF (NSTAGE * STAGE_B)         // 49152
#define SMEM_BYTES (BIAS_OFF + 512)         // 49664
#define NIT 32

struct Job {
    const __half2* A1; const __half2* A2;   // fp16 permuted [512][256]
    const float*   W1; const float*   W2;   // fp32 [2048][512] row-major
    const float* b1;   const float* b2;
    float* c; __half2* h16; float* y; float* h32;
};

// A stage via cp.async (fp16 permuted source), 2 chunks/thread (128 thr)
__device__ __forceinline__ void issueA(uint32_t sb, int it, const Job& j,
                                       int m0, int tid) {
    const __half2* Ap = (it < 16) ? j.A1 : j.A2;
    const int kk = (it & 15) << 4;
    const uint32_t as = sb + (it & 3) * STAGE_B;
#pragma unroll
    for (int u2 = 0; u2 < 2; u2++) {
        int idx = tid + u2 * 128;
        int row = idx >> 2, c4 = idx & 3;
        CP_ASYNC16(as + (row << 6) + (c4 << 4),
                   Ap + (size_t)(m0 + row) * 256 + kk + c4 * 4);
    }
}

// W: gather fp32 -> packed half2 regs (16/thread), permutation-compatible
__device__ __forceinline__ void loadW(uint32_t (&buf)[16], int it, const Job& j,
                                      int j0, int tid) {
    if (it >= NIT) return;
    const float* Wp = (it < 16) ? j.W1 : j.W2;
    const int k0 = (it & 15) * 32;
#pragma unroll
    for (int v = 0; v < 4; v++) {
        int idx = tid + 128 * v;
        int r = idx >> 2, cc = idx & 3;
        int grow = (r & 3) * 512 + j0 + (r >> 2);
        const float* base = Wp + (size_t)grow * 512 + k0 + 2 * cc;
#pragma unroll
        for (int jq = 0; jq < 4; jq++) {
            float2 f = *(const float2*)(base + 8 * jq);
            buf[v * 4 + jq] = pk(f.x, f.y);
        }
    }
}

__device__ __forceinline__ void stsW(const uint32_t (&buf)[16], uint32_t sb, int it, int tid) {
    if (it >= NIT) return;
    const uint32_t ws = sb + (it & 3) * STAGE_B + OFF_W;
#pragma unroll
    for (int v = 0; v < 4; v++) {
        int idx = tid + 128 * v;
        int r = idx >> 2, cc = idx & 3;
        uint4 val = make_uint4(buf[v * 4 + 0], buf[v * 4 + 1], buf[v * 4 + 2], buf[v * 4 + 3]);
        STS128(ws + (r << 6) + (cc << 4), val);
    }
}

__global__ __launch_bounds__(128, 2) void lstm_pair(Job jobA, Job jobB) {
    extern __shared__ char smem[];
    const uint32_t sb = smem_u32(smem);
    const Job j = (blockIdx.z == 0) ? jobA : jobB;

    const int tid  = threadIdx.x;
    const int lane = tid & 31;
    const int wid  = tid >> 5;
    const int wm = wid & 1;          // 2 m-groups x 32 rows
    const int wn = wid >> 1;         // 2 n-groups x 64 n_local
    const int r4 = lane >> 2;
    const int u  = lane & 3;
    const int m0 = blockIdx.y * 64;
    const int j0 = blockIdx.x * 32;

    float* smb = (float*)(smem + BIAS_OFF);
    {   // bias: smb[g*32+jj]
        int g = tid >> 5, jj = tid & 31;
        smb[tid] = j.b1[g * 512 + j0 + jj] + j.b2[g * 512 + j0 + jj];
    }

    float acc[2][8][4];
#pragma unroll
    for (int mt = 0; mt < 2; mt++)
#pragma unroll
        for (int nt = 0; nt < 8; nt++)
#pragma unroll
            for (int e = 0; e < 4; e++) acc[mt][nt][e] = 0.f;

    // pipeline prologue
    issueA(sb, 0, j, m0, tid); CP_COMMIT();
    issueA(sb, 1, j, m0, tid); CP_COMMIT();
    issueA(sb, 2, j, m0, tid); CP_COMMIT();
    uint32_t bufA[16], bufB[16];
    loadW(bufA, 0, j, j0, tid);
    loadW(bufB, 1, j, j0, tid);
    stsW(bufA, sb, 0, tid);
    loadW(bufA, 2, j, j0, tid);

    const int aoff0 = ((wm * 32 + r4) << 6) + (u << 4);          // m-tile 0
    const int boff  = ((wn * 64 + r4) << 6) + (u << 4) + OFF_W;

    for (int itp = 0; itp < NIT; itp += 2) {
#pragma unroll
        for (int h = 0; h < 2; h++) {
            const int it = itp + h;
            CP_WAIT2();
            __syncthreads();
            if (it + 3 < NIT) issueA(sb, it + 3, j, m0, tid);
            CP_COMMIT();
            if (h == 0) {   // even it: buffer B
                stsW(bufB, sb, it + 1, tid);
                loadW(bufB, it + 3, j, j0, tid);
            } else {        // odd it: buffer A
                stsW(bufA, sb, it + 1, tid);
                loadW(bufA, it + 3, j, j0, tid);
            }
            const char* st = smem + (it & 3) * STAGE_B;
            uint4 a0lo = *(const uint4*)(st + aoff0);
            uint4 a0hi = *(const uint4*)(st + aoff0 + 512);          // +8 rows
            uint4 a1lo = *(const uint4*)(st + aoff0 + 1024);         // +16 rows
            uint4 a1hi = *(const uint4*)(st + aoff0 + 1536);
#pragma unroll
            for (int nt = 0; nt < 8; nt++) {
                uint4 bb = *(const uint4*)(st + boff + (nt << 9));
                mma_f16(acc[0][nt], a0lo.x, a0hi.x, a0lo.y, a0hi.y, bb.x, bb.y);
                mma_f16(acc[0][nt], a0lo.z, a0hi.z, a0lo.w, a0hi.w, bb.z, bb.w);
                mma_f16(acc[1][nt], a1lo.x, a1hi.x, a1lo.y, a1hi.y, bb.x, bb.y);
                mma_f16(acc[1][nt], a1lo.z, a1hi.z, a1lo.w, a1hi.w, bb.z, bb.w);
            }
        }
    }

    // ---------------- fused LSTM cell epilogue ----------------
    __syncthreads();
    float* smc = (float*)smem;              // [64][33]
    float* smh = (float*)(smem + 8448);     // [64][33]

    for (int i = tid; i < 64 * 32; i += 128) {
        int r = i >> 5, jj = i & 31;
        smc[r * 33 + jj] = j.c[(size_t)(m0 + r) * HDIM + j0 + jj];
    }
    __syncthreads();

    const bool evn = !(u & 1);
#pragma unroll
    for (int mt = 0; mt < 2; mt++) {
        const int row = wm * 32 + mt * 16 + r4 + (evn ? 0 : 8);
#pragma unroll
        for (int nt = 0; nt < 8; nt++) {
            float x0 = __shfl_xor_sync(0xFFFFFFFFu, acc[mt][nt][0], 1);
            float x1 = __shfl_xor_sync(0xFFFFFFFFu, acc[mt][nt][1], 1);
            float x2 = __shfl_xor_sync(0xFFFFFFFFu, acc[mt][nt][2], 1);
            float x3 = __shfl_xor_sync(0xFFFFFFFFu, acc[mt][nt][3], 1);
            int jj = wn * 16 + nt * 2 + (u >> 1);
            float vi = (evn ? acc[mt][nt][0] : x2) + smb[jj];
            float vf = (evn ? acc[mt][nt][1] : x3) + smb[32 + jj];
            float vg = (evn ? x0 : acc[mt][nt][2]) + smb[64 + jj];
            float vo = (evn ? x1 : acc[mt][nt][3]) + smb[96 + jj];
            float ii = fast_sigmoid(vi);
            float ff = fast_sigmoid(vf);
            float gg = fast_tanh(vg);
            float oo = fast_sigmoid(vo);
            float cn = ff * smc[row * 33 + jj] + ii * gg;
            float hn = oo * fast_tanh(cn);
            smc[row * 33 + jj] = cn;
            smh[row * 33 + jj] = hn;
        }
    }
    __syncthreads();

    for (int i = tid; i < 64 * 32; i += 128) {
        int r = i >> 5, jj = i & 31;
        size_t g = (size_t)(m0 + r) * HDIM + j0 + jj;
        j.c[g] = smc[r * 33 + jj];
        float hv = smh[r * 33 + jj];
        if (j.y)   j.y[g]   = hv;
        if (j.h32) j.h32[g] = hv;
    }
    // h16: permuted fp16 layout
    for (int i = tid; i < 64 * 16; i += 128) {
        int r = i >> 4, q = i & 15;
        int p = (q & 3) * 4 + (q >> 2);
        __half2 hv = __floats2half2_rn(smh[r * 33 + 2 * q], smh[r * 33 + 2 * q + 1]);
        j.h16[(size_t)(m0 + r) * 256 + (j0 >> 1) + p] = hv;
    }
}

// fp32 -> fp16 with k-permutation within 32-element blocks (rows of 512)
__global__ __launch_bounds__(256) void conv_half(const float* __restrict__ src,
                                                 __half2* __restrict__ dst, int n_half2) {
    int e = blockIdx.x * 256 + threadIdx.x;
    if (e >= n_half2) return;
    int row = e >> 8;
    int qr = e & 255;
    int blk = qr >> 4, qb = qr & 15;
    int p = (qb & 3) * 4 + (qb >> 2);
    float2 v = ((const float2*)src)[e];
    dst[((size_t)row << 8) + (blk << 4) + p] = __floats2half2_rn(v.x, v.y);
}

__global__ void zero_state() {
    int i = blockIdx.x * 256 + threadIdx.x;
    if (i < 2 * BH2) g_h16[2 * BH2 + i] = __floats2half2_rn(0.f, 0.f);  // parity-1 planes
    if (i < 2 * BH)  g_c[i] = 0.f;
}

// ---------------- host ----------------
extern "C" void kernel_launch(void* const* d_in, const int* in_sizes, int n_in,
                              void* d_out, int out_size)
{
    const float* x    = (const float*)d_in[0];
    const float* W_ih = (const float*)d_in[1];
    const float* W_hh = (const float*)d_in[2];
    const float* b_ih = (const float*)d_in[3];
    const float* b_hh = (const float*)d_in[4];
    float* out = (float*)d_out;

    __half2 *x16, *h16;
    float* cbuf;
    cudaGetSymbolAddress((void**)&x16,  g_x16);
    cudaGetSymbolAddress((void**)&h16,  g_h16);
    cudaGetSymbolAddress((void**)&cbuf, g_c);

    cudaFuncSetAttribute(lstm_pair, cudaFuncAttributeMaxDynamicSharedMemorySize, SMEM_BYTES);

    const int nX = NSTEPS * BH2;
    conv_half<<<(nX + 255) / 256, 256>>>(x, x16, nX);
    zero_state<<<(2 * BH + 255) / 256, 256>>>();

    auto mkL0 = [&](int t) -> Job {
        int xt = (t < NSTEPS - 1) ? t : NSTEPS - 2;    // source bug: step 29 reuses x[28]
        int wp = t & 1, rp = wp ^ 1;
        Job jb;
        jb.A1 = x16 + (size_t)xt * BH2;
        jb.A2 = h16 + (size_t)(rp * 2 + 0) * BH2;
        jb.W1 = W_ih + (size_t)(t * 2 + 0) * WSZ;
        jb.W2 = W_hh + (size_t)(t * 2 + 0) * WSZ;
        jb.b1 = b_ih + (size_t)(t * 2 + 0) * GDIM;
        jb.b2 = b_hh + (size_t)(t * 2 + 0) * GDIM;
        jb.c  = cbuf;
        jb.h16 = h16 + (size_t)(wp * 2 + 0) * BH2;
        jb.y = nullptr;
        jb.h32 = (t == NSTEPS - 1) ? (out + (size_t)NSTEPS * BH) : nullptr;
        return jb;
    };
    auto mkL1 = [&](int t) -> Job {
        int wp = t & 1, rp = wp ^ 1;
        Job jb;
        jb.A1 = h16 + (size_t)(wp * 2 + 0) * BH2;
        jb.A2 = h16 + (size_t)(rp * 2 + 1) * BH2;
        jb.W1 = W_ih + (size_t)(t * 2 + 1) * WSZ;
        jb.W2 = W_hh + (size_t)(t * 2 + 1) * WSZ;
        jb.b1 = b_ih + (size_t)(t * 2 + 1) * GDIM;
        jb.b2 = b_hh + (size_t)(t * 2 + 1) * GDIM;
        jb.c  = cbuf + BH;
        jb.h16 = h16 + (size_t)(wp * 2 + 1) * BH2;
        jb.y = out + (size_t)t * BH;
        jb.h32 = (t == NSTEPS - 1) ? (out + (size_t)(NSTEPS + 1) * BH) : nullptr;
        return jb;
    };

    // C(0): L0(0); C(k)=L0(k)+L1(k-1); C(30): L1(29)
    {
        Job a = mkL0(0);
        lstm_pair<<<dim3(16, 8, 1), 128, SMEM_BYTES>>>(a, a);
    }
    for (int k = 1; k < NSTEPS; k++) {
        Job a = mkL0(k), b = mkL1(k - 1);
        lstm_pair<<<dim3(16, 8, 2), 128, SMEM_BYTES>>>(a, b);
    }
    {
        Job a = mkL1(NSTEPS - 1);
        lstm_pair<<<dim3(16, 8, 1), 128, SMEM_BYTES>>>(a, a);
    }

    // c planes -> output tail
    cudaMemcpyAsync(out + (size_t)(NSTEPS + 2) * BH, cbuf,
                    2 * BH * sizeof(float), cudaMemcpyDeviceToDevice);
}

// round 7
// speedup vs baseline: 1.6472x; 1.6472x over previous
#include <cuda_runtime.h>
#include <cuda_fp16.h>
#include <cstdint>
#include <math.h>

#define HDIM   512
#define BDIM   512
#define GDIM   2048
#define NSTEPS 30
#define BH     (BDIM * HDIM)
#define BH2    (BDIM * 256)          // half2 per [512,512] plane
#define WPL2   (2048 * 256)          // half2 per [2048,512] weight plane

// fp16 k-permuted copies (pre-converted each launch)
__device__ __align__(1024) __half2 g_w16ih[60 * WPL2];   // 125.8 MB
__device__ __align__(1024) __half2 g_w16hh[60 * WPL2];   // 125.8 MB
__device__ __align__(1024) __half2 g_x16[NSTEPS * BH2];  // 15.7 MB
__device__ __align__(1024) __half2 g_h16[4 * BH2];       // [parity][layer], 2 MB
__device__ __align__(1024) float   g_c[2 * BH];          // 2 MB

// ---------------- helpers ----------------
__device__ __forceinline__ uint32_t smem_u32(const void* p) {
    uint32_t a;
    asm("{ .reg .u64 t; cvta.to.shared.u64 t, %1; cvt.u32.u64 %0, t; }" : "=r"(a) : "l"(p));
    return a;
}
#define CP_ASYNC16(dst_u32, src_ptr) \
    asm volatile("cp.async.cg.shared.global [%0], [%1], 16;" \
                 :: "r"(dst_u32), "l"(src_ptr) : "memory")
#define CP_COMMIT() asm volatile("cp.async.commit_group;" ::: "memory")
#define CP_WAIT2()  asm volatile("cp.async.wait_group 2;" ::: "memory")

__device__ __forceinline__ void mma_f16(float* d,
                                        uint32_t a0, uint32_t a1, uint32_t a2, uint32_t a3,
                                        uint32_t b0, uint32_t b1) {
    asm volatile(
        "mma.sync.aligned.m16n8k16.row.col.f32.f16.f16.f32 "
        "{%0,%1,%2,%3}, {%4,%5,%6,%7}, {%8,%9}, {%0,%1,%2,%3};"
        : "+f"(d[0]), "+f"(d[1]), "+f"(d[2]), "+f"(d[3])
        : "r"(a0), "r"(a1), "r"(a2), "r"(a3), "r"(b0), "r"(b1));
}
__device__ __forceinline__ float fast_sigmoid(float x) {
    return __fdividef(1.0f, 1.0f + __expf(-x));
}
__device__ __forceinline__ float fast_tanh(float x) {
    return 1.0f - __fdividef(2.0f, __expf(2.0f * x) + 1.0f);
}

// ---------------- smem layout (bytes) ----------------
// stage: A 64x32 half = 4096 + W 128x32 half = 8192 -> 12288; 4 stages
#define STAGE_B   12288
#define OFF_W     4096
#define SMC_OFF   49152                 // c tile [64][36] floats = 9216 B
#define BIAS_OFF  58368                 // 512 B
#define SMEM_BYTES 58880
#define NIT 32                          // K = 1024 / 32
#define CPAD 36                         // smc/smh row stride in floats

struct Job {
    const __half2* A1; const __half2* A2;   // fp16 permuted [512][256]
    const __half2* W1; const __half2* W2;   // fp16 permuted [2048][256]
    const float* b1;   const float* b2;
    float* c; __half2* h16; float* y; float* h32;
};

__device__ __forceinline__ void issue_stage(uint32_t sb, int it, const Job& j,
                                            int m0, int j0, int tid) {
    const int s = it & 3;
    const __half2* Ap = (it < 16) ? j.A1 : j.A2;
    const __half2* Wp = (it < 16) ? j.W1 : j.W2;
    const int kk = (it & 15) << 4;              // half2 offset in row
    const uint32_t as = sb + s * STAGE_B;
    const uint32_t ws = as + OFF_W;
    {   // A: 64 rows x 4 chunks = 256 tasks, 1/thread
        int row = tid >> 2, u = tid & 3;
        CP_ASYNC16(as + (row << 6) + (u << 4),
                   Ap + (size_t)(m0 + row) * 256 + kk + u * 4);
    }
#pragma unroll
    for (int t2 = 0; t2 < 2; t2++) {            // W: 128 rows x 4 chunks = 512 tasks, 2/thread
        int idx = tid + t2 * 256;
        int r = idx >> 2, u = idx & 3;
        int grow = (r & 3) * 512 + j0 + (r >> 2);   // n_local -> g*512 + j0 + jj
        CP_ASYNC16(ws + (r << 6) + (u << 4),
                   Wp + (size_t)grow * 256 + kk + u * 4);
    }
}

__global__ __launch_bounds__(256, 2) void lstm_pair(Job jobA, Job jobB) {
    extern __shared__ char smem[];
    const uint32_t sb = smem_u32(smem);
    const Job j = (blockIdx.z == 0) ? jobA : jobB;

    const int tid  = threadIdx.x;
    const int lane = tid & 31;
    const int wid  = tid >> 5;
    const int wm = wid & 1;          // 2 m-groups x 32 rows
    const int wn = wid >> 1;         // 4 n-groups x 32 n_local
    const int r4 = lane >> 2;
    const int u  = lane & 3;
    const int m0 = blockIdx.y * 64;
    const int j0 = blockIdx.x * 32;

    float* smb = (float*)(smem + BIAS_OFF);
    if (tid < 128) {   // bias: smb[g*32+jj]   (guard is load-bearing: smb is 128 floats)
        int g = tid >> 5, jj = tid & 31;
        smb[tid] = j.b1[g * 512 + j0 + jj] + j.b2[g * 512 + j0 + jj];
    }

    float acc[2][4][4];
#pragma unroll
    for (int mt = 0; mt < 2; mt++)
#pragma unroll
        for (int nt = 0; nt < 4; nt++)
#pragma unroll
            for (int e = 0; e < 4; e++) acc[mt][nt][e] = 0.f;

    // prologue: prefetch c (folded into stage-0 group), then stages 0..2
    {
        const uint32_t smc_a = sb + SMC_OFF;
#pragma unroll
        for (int v = 0; v < 2; v++) {
            int idx = tid + v * 256;
            int r = idx >> 3, ch = idx & 7;
            CP_ASYNC16(smc_a + r * (CPAD * 4) + (ch << 4),
                       j.c + (size_t)(m0 + r) * HDIM + j0 + ch * 4);
        }
    }
    issue_stage(sb, 0, j, m0, j0, tid); CP_COMMIT();
    issue_stage(sb, 1, j, m0, j0, tid); CP_COMMIT();
    issue_stage(sb, 2, j, m0, j0, tid); CP_COMMIT();

    const int aoff = ((wm * 32 + r4) << 6) + (u << 4);
    const int boff = ((wn * 32 + r4) << 6) + (u << 4) + OFF_W;

    for (int it = 0; it < NIT; it++) {
        CP_WAIT2();
        __syncthreads();
        if (it + 3 < NIT) issue_stage(sb, it + 3, j, m0, j0, tid);
        CP_COMMIT();   // empty tail groups keep wait accounting uniform

        const char* st = smem + (it & 3) * STAGE_B;
        uint4 a0lo = *(const uint4*)(st + aoff);
        uint4 a0hi = *(const uint4*)(st + aoff + 512);    // +8 rows
        uint4 a1lo = *(const uint4*)(st + aoff + 1024);   // +16 rows
        uint4 a1hi = *(const uint4*)(st + aoff + 1536);   // +24 rows
#pragma unroll
        for (int nt = 0; nt < 4; nt++) {
            uint4 bb = *(const uint4*)(st + boff + (nt << 9));
            mma_f16(acc[0][nt], a0lo.x, a0hi.x, a0lo.y, a0hi.y, bb.x, bb.y);
            mma_f16(acc[0][nt], a0lo.z, a0hi.z, a0lo.w, a0hi.w, bb.z, bb.w);
            mma_f16(acc[1][nt], a1lo.x, a1hi.x, a1lo.y, a1hi.y, bb.x, bb.y);
            mma_f16(acc[1][nt], a1lo.z, a1hi.z, a1lo.w, a1hi.w, bb.z, bb.w);
        }
    }

    // ---------------- fused LSTM cell epilogue ----------------
    __syncthreads();
    float* smc = (float*)(smem + SMC_OFF);   // [64][36], prefetched during mainloop
    float* smh = (float*)smem;               // [64][36] overlays stage region

    const bool evn = !(u & 1);
#pragma unroll
    for (int mt = 0; mt < 2; mt++) {
        const int row = wm * 32 + mt * 16 + r4 + (evn ? 0 : 8);
#pragma unroll
        for (int nt = 0; nt < 4; nt++) {
            float x0 = __shfl_xor_sync(0xFFFFFFFFu, acc[mt][nt][0], 1);
            float x1 = __shfl_xor_sync(0xFFFFFFFFu, acc[mt][nt][1], 1);
            float x2 = __shfl_xor_sync(0xFFFFFFFFu, acc[mt][nt][2], 1);
            float x3 = __shfl_xor_sync(0xFFFFFFFFu, acc[mt][nt][3], 1);
            int jj = wn * 8 + nt * 2 + (u >> 1);
            float vi = (evn ? acc[mt][nt][0] : x2) + smb[jj];
            float vf = (evn ? acc[mt][nt][1] : x3) + smb[32 + jj];
            float vg = (evn ? x0 : acc[mt][nt][2]) + smb[64 + jj];
            float vo = (evn ? x1 : acc[mt][nt][3]) + smb[96 + jj];
            float ii = fast_sigmoid(vi);
            float ff = fast_sigmoid(vf);
            float gg = fast_tanh(vg);
            float oo = fast_sigmoid(vo);
            float cn = ff * smc[row * CPAD + jj] + ii * gg;
            float hn = oo * fast_tanh(cn);
            smc[row * CPAD + jj] = cn;
            smh[row * CPAD + jj] = hn;
        }
    }
    __syncthreads();

    for (int i = tid; i < 64 * 32; i += 256) {
        int r = i >> 5, jj = i & 31;
        size_t g = (size_t)(m0 + r) * HDIM + j0 + jj;
        j.c[g] = smc[r * CPAD + jj];
        float hv = smh[r * CPAD + jj];
        if (j.y)   j.y[g]   = hv;
        if (j.h32) j.h32[g] = hv;
    }
    // h16: permuted fp16 layout
    for (int i = tid; i < 64 * 16; i += 256) {
        int r = i >> 4, q = i & 15;
        int p = (q & 3) * 4 + (q >> 2);
        __half2 hv = __floats2half2_rn(smh[r * CPAD + 2 * q], smh[r * CPAD + 2 * q + 1]);
        j.h16[(size_t)(m0 + r) * 256 + (j0 >> 1) + p] = hv;
    }
}

// fp32 -> fp16 with k-permutation within 32-element blocks (rows of 512)
__global__ __launch_bounds__(256) void conv_half(const float* __restrict__ src,
                                                 __half2* __restrict__ dst, int n_half2) {
    int e = blockIdx.x * 256 + threadIdx.x;
    if (e >= n_half2) return;
    int row = e >> 8;
    int qr = e & 255;
    int blk = qr >> 4, qb = qr & 15;
    int p = (qb & 3) * 4 + (qb >> 2);
    float2 v = ((const float2*)src)[e];
    dst[((size_t)row << 8) + (blk << 4) + p] = __floats2half2_rn(v.x, v.y);
}

__global__ void zero_state() {
    int i = blockIdx.x * 256 + threadIdx.x;
    if (i < 2 * BH2) g_h16[2 * BH2 + i] = __floats2half2_rn(0.f, 0.f);  // parity-1 planes
    if (i < 2 * BH)  g_c[i] = 0.f;
}

// ---------------- host ----------------
extern "C" void kernel_launch(void* const* d_in, const int* in_sizes, int n_in,
                              void* d_out, int out_size)
{
    const float* x    = (const float*)d_in[0];
    const float* W_ih = (const float*)d_in[1];
    const float* W_hh = (const float*)d_in[2];
    const float* b_ih = (const float*)d_in[3];
    const float* b_hh = (const float*)d_in[4];
    float* out = (float*)d_out;

    __half2 *w16ih, *w16hh, *x16, *h16;
    float* cbuf;
    cudaGetSymbolAddress((void**)&w16ih, g_w16ih);
    cudaGetSymbolAddress((void**)&w16hh, g_w16hh);
    cudaGetSymbolAddress((void**)&x16,   g_x16);
    cudaGetSymbolAddress((void**)&h16,   g_h16);
    cudaGetSymbolAddress((void**)&cbuf,  g_c);

    cudaFuncSetAttribute(lstm_pair, cudaFuncAttributeMaxDynamicSharedMemorySize, SMEM_BYTES);

    const int nW = 60 * WPL2;
    const int nX = NSTEPS * BH2;
    conv_half<<<(nW + 255) / 256, 256>>>(W_ih, w16ih, nW);
    conv_half<<<(nW + 255) / 256, 256>>>(W_hh, w16hh, nW);
    conv_half<<<(nX + 255) / 256, 256>>>(x, x16, nX);
    zero_state<<<(2 * BH + 255) / 256, 256>>>();

    auto mkL0 = [&](int t) -> Job {
        int xt = (t < NSTEPS - 1) ? t : NSTEPS - 2;    // source bug: step 29 reuses x[28]
        int wp = t & 1, rp = wp ^ 1;
        Job jb;
        jb.A1 = x16 + (size_t)xt * BH2;
        jb.A2 = h16 + (size_t)(rp * 2 + 0) * BH2;
        jb.W1 = w16ih + (size_t)(t * 2 + 0) * WPL2;
        jb.W2 = w16hh + (size_t)(t * 2 + 0) * WPL2;
        jb.b1 = b_ih + (size_t)(t * 2 + 0) * GDIM;
        jb.b2 = b_hh + (size_t)(t * 2 + 0) * GDIM;
        jb.c  = cbuf;
        jb.h16 = h16 + (size_t)(wp * 2 + 0) * BH2;
        jb.y = nullptr;
        jb.h32 = (t == NSTEPS - 1) ? (out + (size_t)NSTEPS * BH) : nullptr;
        return jb;
    };
    auto mkL1 = [&](int t) -> Job {
        int wp = t & 1, rp = wp ^ 1;
        Job jb;
        jb.A1 = h16 + (size_t)(wp * 2 + 0) * BH2;
        jb.A2 = h16 + (size_t)(rp * 2 + 1) * BH2;
        jb.W1 = w16ih + (size_t)(t * 2 + 1) * WPL2;
        jb.W2 = w16hh + (size_t)(t * 2 + 1) * WPL2;
        jb.b1 = b_ih + (size_t)(t * 2 + 1) * GDIM;
        jb.b2 = b_hh + (size_t)(t * 2 + 1) * GDIM;
        jb.c  = cbuf + BH;
        jb.h16 = h16 + (size_t)(wp * 2 + 1) * BH2;
        jb.y = out + (size_t)t * BH;
        jb.h32 = (t == NSTEPS - 1) ? (out + (size_t)(NSTEPS + 1) * BH) : nullptr;
        return jb;
    };

    // C(0): L0(0); C(k)=L0(k)+L1(k-1); C(30): L1(29)
    {
        Job a = mkL0(0);
        lstm_pair<<<dim3(16, 8, 1), 256, SMEM_BYTES>>>(a, a);
    }
    for (int k = 1; k < NSTEPS; k++) {
        Job a = mkL0(k), b = mkL1(k - 1);
        lstm_pair<<<dim3(16, 8, 2), 256, SMEM_BYTES>>>(a, b);
    }
    {
        Job a = mkL1(NSTEPS - 1);
        lstm_pair<<<dim3(16, 8, 1), 256, SMEM_BYTES>>>(a, a);
    }

    // c planes -> output tail
    cudaMemcpyAsync(out + (size_t)(NSTEPS + 2) * BH, cbuf,
                    2 * BH * sizeof(float), cudaMemcpyDeviceToDevice);
}